// round 5
// baseline (speedup 1.0000x reference)
#include <cuda_runtime.h>

#define B_CHAIN 16384
#define S_SIDE 15
#define NATM (1 + B_CHAIN + B_CHAIN * S_SIDE)
#define GEN1_BASE (1 + B_CHAIN)

#define TPB_A 128
#define NBLK_A (B_CHAIN / TPB_A)   // 128

// Scratch (static __device__ arrays — no allocation).
__device__ __align__(16) float g_scan[(B_CHAIN + 1) * 12];  // inclusive-within-kA-block
__device__ __align__(16) float g_blk[NBLK_A * 12];          // kA block totals
__device__ __align__(16) float g_pre[NBLK_A * 12];          // exclusive block prefixes

// Affine 3x4: m[0..8] row-major rotation, m[9..11] translation. c = a*b (a earlier in chain).
__device__ __forceinline__ void aff_mul(const float a[12], const float b[12], float c[12]) {
#pragma unroll
    for (int i = 0; i < 3; i++) {
        float a0 = a[i * 3 + 0], a1 = a[i * 3 + 1], a2 = a[i * 3 + 2];
        float t  = a[9 + i];
        c[i * 3 + 0] = a0 * b[0] + a1 * b[3] + a2 * b[6];
        c[i * 3 + 1] = a0 * b[1] + a1 * b[4] + a2 * b[7];
        c[i * 3 + 2] = a0 * b[2] + a1 * b[5] + a2 * b[8];
        c[9 + i]     = a0 * b[9] + a1 * b[10] + a2 * b[11] + t;
    }
}

__device__ __forceinline__ void aff_identity(float m[12]) {
#pragma unroll
    for (int k = 0; k < 12; k++) m[k] = 0.0f;
    m[0] = m[4] = m[8] = 1.0f;
}

// ht_bond = Rx(p)*Rz(t)*T(d,0,0)*Rx(c), collapsed. Precise trig (backbone:
// error random-walks over 16K products).
__device__ __forceinline__ void make_bond(float p, float t, float d, float c, float m[12]) {
    float sp, cp, st, ct, sc, cc;
    sincosf(p, &sp, &cp);
    sincosf(t, &st, &ct);
    sincosf(c, &sc, &cc);
    m[0] = ct;        m[1] = -st * cc;               m[2] = st * sc;
    m[3] = cp * st;   m[4] = cp * ct * cc - sp * sc; m[5] = -cp * ct * sc - sp * cc;
    m[6] = sp * st;   m[7] = sp * ct * cc + cp * sc; m[8] = -sp * ct * sc + cp * cc;
    m[9] = ct * d;    m[10] = cp * st * d;           m[11] = sp * st * d;
}

// Fast-trig variant (side chains: 15-product chains, no accumulation).
__device__ __forceinline__ void make_bond_fast(float p, float t, float d, float c, float m[12]) {
    float sp, cp, st, ct, sc, cc;
    __sincosf(p, &sp, &cp);
    __sincosf(t, &st, &ct);
    __sincosf(c, &sc, &cc);
    m[0] = ct;        m[1] = -st * cc;               m[2] = st * sc;
    m[3] = cp * st;   m[4] = cp * ct * cc - sp * sc; m[5] = -cp * ct * sc - sp * cc;
    m[6] = sp * st;   m[7] = sp * ct * cc + cp * sc; m[8] = -sp * ct * sc + cp * cc;
    m[9] = ct * d;    m[10] = cp * st * d;           m[11] = sp * st * d;
}

__device__ __forceinline__ void make_ht(int atom, float4 dv, float m[12]) {
    if (atom == 1) {   // jump node: T(d0,d1,d2)*Rx(d3)
        float sc, cc;
        sincosf(dv.w, &sc, &cc);
        m[0] = 1.f; m[1] = 0.f; m[2] = 0.f;
        m[3] = 0.f; m[4] = cc;  m[5] = -sc;
        m[6] = 0.f; m[7] = sc;  m[8] = cc;
        m[9] = dv.x; m[10] = dv.y; m[11] = dv.z;
    } else {
        make_bond(dv.x, dv.y, dv.z, dv.w, m);
    }
}

__device__ __forceinline__ void store12(float* dst, const float m[12]) {
    float4* d4 = (float4*)dst;
    d4[0] = make_float4(m[0], m[1], m[2], m[3]);
    d4[1] = make_float4(m[4], m[5], m[6], m[7]);
    d4[2] = make_float4(m[8], m[9], m[10], m[11]);
}

__device__ __forceinline__ void load12(const float* src, float m[12]) {
    const float4* s4 = (const float4*)src;
    float4 a = s4[0], b = s4[1], c = s4[2];
    m[0] = a.x; m[1] = a.y; m[2] = a.z; m[3] = a.w;
    m[4] = b.x; m[5] = b.y; m[6] = b.z; m[7] = b.w;
    m[8] = c.x; m[9] = c.y; m[10] = c.z; m[11] = c.w;
}

// Warp-level inclusive Kogge-Stone (32 lanes, 5 steps), no barriers.
__device__ __forceinline__ void warp_scan32(float P[12], int lane) {
#pragma unroll
    for (int d = 1; d < 32; d <<= 1) {
        float L[12];
#pragma unroll
        for (int k = 0; k < 12; k++)
            L[k] = __shfl_up_sync(0xffffffffu, P[k], d, 32);
        if (lane >= d) {
            float T[12];
            aff_mul(L, P, T);
#pragma unroll
            for (int k = 0; k < 12; k++) P[k] = T[k];
        }
    }
}

// ---------------------------------------------------------------------------
// kA: backbone ht build + block-inclusive scan. 128 blocks x 128 threads.
// warp shfl scan -> 4-warp-total combine (warp 0) -> apply. 2 barriers.
// ---------------------------------------------------------------------------
__global__ void __launch_bounds__(TPB_A) kA_block_scan(const float* __restrict__ dofs) {
    __shared__ float wt[4 * 12];
    int t = threadIdx.x;
    int w = t >> 5, l = t & 31;
    int atom = blockIdx.x * TPB_A + t + 1;

    float4 dv = ((const float4*)dofs)[atom - 1];
    float P[12];
    make_ht(atom, dv, P);

    warp_scan32(P, l);

    if (l == 31) {
#pragma unroll
        for (int k = 0; k < 12; k++) wt[w * 12 + k] = P[k];
    }
    __syncthreads();

    if (w == 0 && l < 4) {   // scan the 4 warp totals
        float Q[12];
#pragma unroll
        for (int k = 0; k < 12; k++) Q[k] = wt[l * 12 + k];
#pragma unroll
        for (int d = 1; d < 4; d <<= 1) {
            float L[12];
#pragma unroll
            for (int k = 0; k < 12; k++)
                L[k] = __shfl_up_sync(0x0000000fu, Q[k], d, 4);
            if (l >= d) {
                float T[12];
                aff_mul(L, Q, T);
#pragma unroll
                for (int k = 0; k < 12; k++) Q[k] = T[k];
            }
        }
#pragma unroll
        for (int k = 0; k < 12; k++) wt[l * 12 + k] = Q[k];
    }
    __syncthreads();

    if (w > 0) {
        float E[12], T[12];
#pragma unroll
        for (int k = 0; k < 12; k++) E[k] = wt[(w - 1) * 12 + k];
        aff_mul(E, P, T);
#pragma unroll
        for (int k = 0; k < 12; k++) P[k] = T[k];
    }

    store12(g_scan + atom * 12, P);
    if (t == TPB_A - 1) store12(g_blk + blockIdx.x * 12, P);
}

// ---------------------------------------------------------------------------
// kB: scan the 128 block totals -> g_pre (exclusive prefix per kA block).
// Single block, 128 threads. warp scan + 4-warp combine, then shift by one.
// ---------------------------------------------------------------------------
__global__ void __launch_bounds__(TPB_A) kB_block_prefix() {
    __shared__ float wt[4 * 12];
    __shared__ float inc[NBLK_A * 12];
    int t = threadIdx.x;
    int w = t >> 5, l = t & 31;

    float P[12];
    load12(g_blk + t * 12, P);
    warp_scan32(P, l);

    if (l == 31) {
#pragma unroll
        for (int k = 0; k < 12; k++) wt[w * 12 + k] = P[k];
    }
    __syncthreads();

    if (w == 0 && l < 4) {
        float Q[12];
#pragma unroll
        for (int k = 0; k < 12; k++) Q[k] = wt[l * 12 + k];
#pragma unroll
        for (int d = 1; d < 4; d <<= 1) {
            float L[12];
#pragma unroll
            for (int k = 0; k < 12; k++)
                L[k] = __shfl_up_sync(0x0000000fu, Q[k], d, 4);
            if (l >= d) {
                float T[12];
                aff_mul(L, Q, T);
#pragma unroll
                for (int k = 0; k < 12; k++) Q[k] = T[k];
            }
        }
#pragma unroll
        for (int k = 0; k < 12; k++) wt[l * 12 + k] = Q[k];
    }
    __syncthreads();

    if (w > 0) {
        float E[12], T[12];
#pragma unroll
        for (int k = 0; k < 12; k++) E[k] = wt[(w - 1) * 12 + k];
        aff_mul(E, P, T);
#pragma unroll
        for (int k = 0; k < 12; k++) P[k] = T[k];
    }

#pragma unroll
    for (int k = 0; k < 12; k++) inc[t * 12 + k] = P[k];
    __syncthreads();

    float X[12];
    if (t == 0) {
        aff_identity(X);
    } else {
#pragma unroll
        for (int k = 0; k < 12; k++) X[k] = inc[(t - 1) * 12 + k];
    }
    store12(g_pre + t * 12, X);
}

// ---------------------------------------------------------------------------
// kE: raking side-chain scan. 4 lanes per chain, 4 elements per lane.
// Chain elements: e0 = parent global (g_pre[blk]*g_scan[parent]),
//                 e1..e15 = side-chain bond transforms (fast trig).
// Phase 1: dense serial local product (3 muls). Phase 2: width-4 shfl scan
// (2 steps). Phase 3: exclusive via shfl_up(1), 4 apply-muls with bond
// recompute, emit all 16 prefix translations (parent + 15 side atoms).
// No smem, no barriers. Covers every output atom.
// ---------------------------------------------------------------------------
__global__ void __launch_bounds__(256) kE_rake(const float* __restrict__ dofs,
                                              const int* __restrict__ kin_id,
                                              float* __restrict__ out) {
    int g = blockIdx.x * blockDim.x + threadIdx.x;
    int c = g >> 2;        // chain 0..B_CHAIN-1
    int r = g & 3;         // rake lane within chain

    // --- first element of this lane (e_{4r}) ---
    float E0[12];
    if (r == 0) {
        // e0 = parent global = g_pre[block] * g_scan[c+1]
        float pre[12], Sv[12];
        load12(g_pre + (c >> 7) * 12, pre);
        load12(g_scan + (c + 1) * 12, Sv);
        aff_mul(pre, Sv, E0);
    } else {
        int node = GEN1_BASE + c * S_SIDE + (4 * r - 1);
        float4 dv = ((const float4*)dofs)[node - 1];
        make_bond_fast(dv.x, dv.y, dv.z, dv.w, E0);
    }

    // --- phase 1: local product P = E0 * e_{4r+1} * e_{4r+2} * e_{4r+3} ---
    float P[12];
#pragma unroll
    for (int k = 0; k < 12; k++) P[k] = E0[k];
#pragma unroll
    for (int j = 1; j < 4; j++) {
        int node = GEN1_BASE + c * S_SIDE + (4 * r + j - 1);
        float4 dv = ((const float4*)dofs)[node - 1];
        float M[12], T[12];
        make_bond_fast(dv.x, dv.y, dv.z, dv.w, M);
        aff_mul(P, M, T);
#pragma unroll
        for (int k = 0; k < 12; k++) P[k] = T[k];
    }

    // --- phase 2: inclusive scan over the 4 rake lanes (2 steps, width 4) ---
#pragma unroll
    for (int d = 1; d < 4; d <<= 1) {
        float L[12];
#pragma unroll
        for (int k = 0; k < 12; k++)
            L[k] = __shfl_up_sync(0xffffffffu, P[k], d, 4);
        if (r >= d) {
            float T[12];
            aff_mul(L, P, T);
#pragma unroll
            for (int k = 0; k < 12; k++) P[k] = T[k];
        }
    }

    // --- exclusive prefix X for this lane ---
    float X[12];
#pragma unroll
    for (int k = 0; k < 12; k++) X[k] = __shfl_up_sync(0xffffffffu, P[k], 1, 4);
    if (r == 0) aff_identity(X);

    // --- phase 3: apply + emit 4 prefix translations ---
    float G[12];
    {
        float T[12];
        aff_mul(X, E0, T);           // element 4r
#pragma unroll
        for (int k = 0; k < 12; k++) G[k] = T[k];
    }
    {
        int node = (r == 0) ? (c + 1) : (GEN1_BASE + c * S_SIDE + (4 * r - 1));
        int kid = kin_id[node];
        out[kid * 3 + 0] = G[9];
        out[kid * 3 + 1] = G[10];
        out[kid * 3 + 2] = G[11];
    }
#pragma unroll
    for (int j = 1; j < 4; j++) {
        int node = GEN1_BASE + c * S_SIDE + (4 * r + j - 1);
        float4 dv = ((const float4*)dofs)[node - 1];
        float M[12], T[12];
        make_bond_fast(dv.x, dv.y, dv.z, dv.w, M);
        aff_mul(G, M, T);
#pragma unroll
        for (int k = 0; k < 12; k++) G[k] = T[k];
        int kid = kin_id[node];
        out[kid * 3 + 0] = G[9];
        out[kid * 3 + 1] = G[10];
        out[kid * 3 + 2] = G[11];
    }
}

extern "C" void kernel_launch(void* const* d_in, const int* in_sizes, int n_in,
                              void* d_out, int out_size) {
    const float* dofs   = (const float*)d_in[0];
    const int*   kin_id = (const int*)d_in[8];
    float*       out    = (float*)d_out;

    kA_block_scan<<<NBLK_A, TPB_A>>>(dofs);
    kB_block_prefix<<<1, TPB_A>>>();
    kE_rake<<<(B_CHAIN * 4) / 256, 256>>>(dofs, kin_id, out);
}